// round 16
// baseline (speedup 1.0000x reference)
#include <cuda_runtime.h>
#include <cuda_bf16.h>
#include <math.h>
#include <stdint.h>

#define NN 50000
#define EE 800000
#define HH 128
#define LL 3
#define NT 256
#define EPSBN 1e-5f

// ---------------- scratch ---------------------------------------------------
__device__ float    g_h[NN * HH];
__device__ unsigned g_pb[NN * 64];     // P in bf16x2
__device__ float    g_agg[NN * HH];
__device__ unsigned g_ub[NN * 64];     // U in bf16x2
__device__ float    g_r[NN * HH];
__device__ int      g_cnt[NN];
__device__ int      g_fill[NN];
__device__ int      g_eoff[NN + 1];
__device__ int      g_bsum[128];
__device__ int      g_esrc[EE];
__device__ int      g_edst[EE];
__device__ float2   g_eea[EE];
__device__ float    g_sum[LL * HH];
__device__ float    g_sq[LL * HH];
// bf16 B-fragment tables (global-resident, stride 128/group)
__device__ unsigned g_w1af[LL * 8192];    // W1a top (K=128)
__device__ unsigned g_w1bf[LL * 8192];    // W1b     (K=128)
__device__ unsigned g_w2af[LL * 16384];   // W2a     (K=256)
__device__ unsigned g_w2bf[LL * 8192];    // W2b     (K=128)

// ---------------- mma / ldmatrix helpers -------------------------------------
__device__ __forceinline__ unsigned f2tf32(float f) {
    unsigned u;
    asm("cvt.rna.tf32.f32 %0, %1;" : "=r"(u) : "f"(f));
    return u;
}
__device__ __forceinline__ void mma8(float acc[4], const uint4& a,
                                     unsigned b0, unsigned b1) {
    asm volatile(
        "mma.sync.aligned.m16n8k8.row.col.f32.tf32.tf32.f32 "
        "{%0,%1,%2,%3},{%4,%5,%6,%7},{%8,%9},{%0,%1,%2,%3};\n"
        : "+f"(acc[0]), "+f"(acc[1]), "+f"(acc[2]), "+f"(acc[3])
        : "r"(a.x), "r"(a.y), "r"(a.z), "r"(a.w), "r"(b0), "r"(b1));
}
__device__ __forceinline__ void mma16(float acc[4], const uint4& a,
                                      unsigned b0, unsigned b1) {
    asm volatile(
        "mma.sync.aligned.m16n8k16.row.col.f32.bf16.bf16.f32 "
        "{%0,%1,%2,%3},{%4,%5,%6,%7},{%8,%9},{%0,%1,%2,%3};\n"
        : "+f"(acc[0]), "+f"(acc[1]), "+f"(acc[2]), "+f"(acc[3])
        : "r"(a.x), "r"(a.y), "r"(a.z), "r"(a.w), "r"(b0), "r"(b1));
}
__device__ __forceinline__ uint4 ldsm4(unsigned addr) {
    uint4 r;
    asm volatile("ldmatrix.sync.aligned.m8n8.x4.shared.b16 {%0,%1,%2,%3}, [%4];"
        : "=r"(r.x), "=r"(r.y), "=r"(r.z), "=r"(r.w) : "r"(addr));
    return r;
}
// tf32 A-frag lane address (fp32 row-major, lda floats)
__device__ __forceinline__ unsigned a_lane_addr(const float* As, int lda,
                                                int q, int lane) {
    return (unsigned)__cvta_generic_to_shared(As)
         + ((((q * 16 + (lane & 15)) * lda) + 4 * (lane >> 4)) << 2);
}
// bf16 row-major A tile, stride in BYTES
__device__ __forceinline__ unsigned a_lane_addr_bf(const void* As, int strideB,
                                                   int q, int lane) {
    return (unsigned)__cvta_generic_to_shared(As)
         + (q * 16 + (lane & 7) + 8 * ((lane >> 3) & 1)) * strideB
         + (lane >> 4) * 16;
}

// KxN(128) fp32 weight -> tf32 B fragments (smem path, k_input/k_final only)
__device__ __forceinline__ void stage_w_frag(float* Wf, const float* __restrict__ Wg,
                                             int KS, int tid)
{
    const int total = 2 * KS * 4 * 132;
    for (int i = tid; i < total; i += NT) {
        int grp = i / 132, off = i % 132;
        if (off < 128) {
            int s = off & 3, t = off >> 2;
            int gg = t >> 2, tt = t & 3;
            int hh = grp / (KS * 4);
            int rem = grp - hh * (KS * 4);
            int ks = rem >> 2, p = rem & 3;
            int k = 8 * ks + tt + ((s & 1) ? 4 : 0);
            int n = hh * 64 + 16 * p + gg + ((s >= 2) ? 8 : 0);
            Wf[i] = __uint_as_float(f2tf32(Wg[(size_t)k * 128 + n]));
        }
    }
}

// ---------------- one-shot: all weights -> global bf16 fragments -------------
__device__ __forceinline__ unsigned frag_val(const float* __restrict__ Wg,
                                             int KS, int idx)
{
    int grp = idx >> 7, off = idx & 127;
    int s = off & 3, lane = off >> 2;
    int g = lane >> 2, t = lane & 3;
    int hh = grp / (KS * 4);
    int rem = grp - hh * (KS * 4);
    int ks = rem >> 2, pp = rem & 3;
    int p = 2 * pp + (s >> 1);
    int bsel = s & 1;
    int n = hh * 64 + p * 8 + g;
    int k0 = ks * 16 + 2 * t + 8 * bsel;
    __nv_bfloat162 v = __floats2bfloat162_rn(Wg[(size_t)k0 * 128 + n],
                                             Wg[(size_t)(k0 + 1) * 128 + n]);
    return *(unsigned*)&v;
}
__global__ void k_wprep(const float* __restrict__ W1a,
                        const float* __restrict__ W1b,
                        const float* __restrict__ W2a,
                        const float* __restrict__ W2b)
{
    int i = blockIdx.x * blockDim.x + threadIdx.x;
    if (i >= LL * 40960) return;
    int l = i / 40960, r = i - l * 40960;
    if (r < 8192)
        g_w1af[l * 8192 + r]  = frag_val(W1a + (size_t)l * 130 * 128, 8, r);
    else if (r < 16384)
        g_w1bf[l * 8192 + (r - 8192)] = frag_val(W1b + (size_t)l * 128 * 128, 8, r - 8192);
    else if (r < 32768)
        g_w2af[l * 16384 + (r - 16384)] = frag_val(W2a + (size_t)l * 256 * 128, 16, r - 16384);
    else
        g_w2bf[l * 8192 + (r - 32768)] = frag_val(W2b + (size_t)l * 128 * 128, 8, r - 32768);
}

// ---------------- zero init --------------------------------------------------
__global__ void k_zero(int n)
{
    int total = n * HH;
    for (int i = blockIdx.x * blockDim.x + threadIdx.x; i < total;
         i += gridDim.x * blockDim.x) {
        g_agg[i] = 0.f;
        if (i < n) { g_cnt[i] = 0; g_fill[i] = 0; }
        if (i < LL * HH) { g_sum[i] = 0.f; g_sq[i] = 0.f; }
    }
}

// ---------------- fast two-level scan ----------------------------------------
__global__ void k_scanA(int n)
{
    __shared__ int buf[1024];
    const int tid = threadIdx.x;
    const int base = blockIdx.x * 1024;
    int v = (base + tid < n) ? g_cnt[base + tid] : 0;
    buf[tid] = v;
    __syncthreads();
    for (int off = 1; off < 1024; off <<= 1) {
        int t = (tid >= off) ? buf[tid - off] : 0;
        __syncthreads();
        buf[tid] += t;
        __syncthreads();
    }
    if (base + tid < n) g_eoff[base + tid] = buf[tid];
    if (tid == 1023) g_bsum[blockIdx.x] = buf[1023];
}
__global__ void k_scanB(int nb, int n)
{
    __shared__ int buf[128];
    const int tid = threadIdx.x;
    int v = (tid < nb) ? g_bsum[tid] : 0;
    buf[tid] = v;
    __syncthreads();
    for (int off = 1; off < 128; off <<= 1) {
        int t = (tid >= off) ? buf[tid - off] : 0;
        __syncthreads();
        buf[tid] += t;
        __syncthreads();
    }
    if (tid < nb) g_bsum[tid] = buf[tid] - v;
    if (tid == 127) g_eoff[n] = buf[127];
}
__global__ void k_scanC(int n)
{
    int i = blockIdx.x * blockDim.x + threadIdx.x;
    if (i < n) g_eoff[i] = g_eoff[i] - g_cnt[i] + g_bsum[i >> 10];
}

// ---------------- counting-sort scatter --------------------------------------
__global__ void k_sort(const int* __restrict__ src, const int* __restrict__ dst,
                       const float* __restrict__ ea, int E)
{
    int e = blockIdx.x * blockDim.x + threadIdx.x;
    if (e < E) {
        int d = dst[e];
        float2 ev = *(const float2*)(ea + 2 * (size_t)e);
        int slot = g_eoff[d] + atomicAdd(&g_fill[d], 1);
        g_esrc[slot] = src[e];
        g_edst[slot] = d;
        g_eea[slot] = ev;
    }
}

// ---------------- input MLP (tf32 mma) + degree count ------------------------
__global__ void __launch_bounds__(NT, 2) k_input(
    const float* __restrict__ x,
    const float* __restrict__ W0, const float* __restrict__ b0,
    const float* __restrict__ W1, const float* __restrict__ b1,
    const int* __restrict__ dst, int E, int n, int ntiles)
{
    extern __shared__ float smem[];
    float* Wf  = smem;              // 16896
    float* As  = Wf + 16896;        // 64*132
    float* w0s = As + 8448;         // 256
    float* b0s = w0s + 256;         // 128
    float* xs  = b0s + 128;         // 128
    const int tid  = threadIdx.x;
    const int lane = tid & 31, w = tid >> 5;
    const int q = w & 3, h = w >> 2;
    const int g = lane >> 2, tg = lane & 3;

    for (int e = blockIdx.x * blockDim.x + tid; e < E; e += gridDim.x * blockDim.x)
        atomicAdd(&g_cnt[dst[e]], 1);

    stage_w_frag(Wf, W1, 16, tid);
    for (int t = tid; t < 256; t += NT) w0s[t] = W0[t];
    if (tid < 128) b0s[tid] = b0[tid];
    float bv[16];
    #pragma unroll
    for (int nt = 0; nt < 8; ++nt) {
        int col = h * 64 + 8 * nt + 2 * tg;
        bv[2 * nt]     = b1[col];
        bv[2 * nt + 1] = b1[col + 1];
    }
    const unsigned alane = a_lane_addr(As, 132, q, lane);

    for (int tile = blockIdx.x; tile < ntiles; tile += gridDim.x) {
        const int base = tile * 64;
        __syncthreads();
        if (tid < 128)
            xs[tid] = (base + (tid >> 1) < n) ? x[(size_t)base * 2 + tid] : 0.f;
        __syncthreads();

        for (int wi = tid; wi < 2048; wi += NT) {
            int row = wi >> 5, j = (wi & 31) << 2;
            float x0 = xs[row * 2], x1 = xs[row * 2 + 1];
            uint4 st;
            st.x = f2tf32(fmaxf(fmaf(x0, w0s[j+0], fmaf(x1, w0s[128+j+0], b0s[j+0])), 0.f));
            st.y = f2tf32(fmaxf(fmaf(x0, w0s[j+1], fmaf(x1, w0s[128+j+1], b0s[j+1])), 0.f));
            st.z = f2tf32(fmaxf(fmaf(x0, w0s[j+2], fmaf(x1, w0s[128+j+2], b0s[j+2])), 0.f));
            st.w = f2tf32(fmaxf(fmaf(x0, w0s[j+3], fmaf(x1, w0s[128+j+3], b0s[j+3])), 0.f));
            *(uint4*)(As + row * 132 + j) = st;
        }
        __syncthreads();

        float acc[8][4] = {};
        #pragma unroll
        for (int ks = 0; ks < 16; ++ks) {
            uint4 a = ldsm4(alane + (ks << 5));
            #pragma unroll
            for (int p = 0; p < 4; ++p) {
                uint4 b = *(const uint4*)(Wf + ((h * 16 + ks) * 4 + p) * 132 + lane * 4);
                mma8(acc[2 * p],     a, b.x, b.y);
                mma8(acc[2 * p + 1], a, b.z, b.w);
            }
        }

        int r0 = base + q * 16 + g;
        #pragma unroll
        for (int nt = 0; nt < 8; ++nt) {
            int col = h * 64 + 8 * nt + 2 * tg;
            if (r0 < n)
                *(float2*)(g_h + (size_t)r0 * HH + col) =
                    make_float2(fmaxf(acc[nt][0] + bv[2 * nt], 0.f),
                                fmaxf(acc[nt][1] + bv[2 * nt + 1], 0.f));
            if (r0 + 8 < n)
                *(float2*)(g_h + (size_t)(r0 + 8) * HH + col) =
                    make_float2(fmaxf(acc[nt][2] + bv[2 * nt], 0.f),
                                fmaxf(acc[nt][3] + bv[2 * nt + 1], 0.f));
        }
    }
}

// ---------------- P = BN?(h) @ W1a_top : global B fragments, 4 blk/SM ---------
__global__ void __launch_bounds__(NT, 4) k_precompute(
    const float* __restrict__ gamma, const float* __restrict__ beta,
    int wl, int bnl, int n, int ntiles)
{
    extern __shared__ float smem[];
    __nv_bfloat16* As = (__nv_bfloat16*)smem;            // 64 x 136 bf16 (4352 w)
    float* scp = (float*)(As + 64 * 136);                // 144
    float* shp = scp + 144;                              // 144
    const int tid  = threadIdx.x;
    const int lane = tid & 31, w = tid >> 5;
    const int q = w & 3, h = w >> 2;
    const int g2 = lane >> 2, tg = lane & 3;

    const unsigned* Wg = g_w1af + (size_t)wl * 8192;
    if (tid < 128) {
        int c = tid >> 3, s = tid & 7;
        if (bnl >= 0) {
            float invn = 1.f / (float)n;
            float mu  = g_sum[bnl * HH + tid] * invn;
            float var = g_sq[bnl * HH + tid] * invn - mu * mu;
            float sv = gamma[tid] * rsqrtf(var + EPSBN);
            scp[c * 9 + s] = sv; shp[c * 9 + s] = beta[tid] - mu * sv;
        } else { scp[c * 9 + s] = 1.f; shp[c * 9 + s] = 0.f; }
    }
    const unsigned alane = a_lane_addr_bf(As, 272, q, lane);
    const int pc = tid & 15;

    for (int tile = blockIdx.x; tile < ntiles; tile += gridDim.x) {
        const int base = tile * 64;
        __syncthreads();
        for (int wi = tid; wi < 1024; wi += NT) {
            int row = wi >> 4, j = pc * 8;
            int node = base + row;
            float v[8] = {0,0,0,0,0,0,0,0};
            if (node < n) {
                float4 va, vb;
                if (bnl >= 0) {
                    va = *(const float4*)(g_r + (size_t)node * HH + j);
                    vb = *(const float4*)(g_r + (size_t)node * HH + j + 4);
                    float vv[8] = {va.x,va.y,va.z,va.w,vb.x,vb.y,vb.z,vb.w};
                    #pragma unroll
                    for (int s = 0; s < 8; ++s)
                        v[s] = vv[s] * scp[pc * 9 + s] + shp[pc * 9 + s];
                    *(float4*)(g_h + (size_t)node * HH + j)     = make_float4(v[0],v[1],v[2],v[3]);
                    *(float4*)(g_h + (size_t)node * HH + j + 4) = make_float4(v[4],v[5],v[6],v[7]);
                } else {
                    va = *(const float4*)(g_h + (size_t)node * HH + j);
                    vb = *(const float4*)(g_h + (size_t)node * HH + j + 4);
                    v[0]=va.x; v[1]=va.y; v[2]=va.z; v[3]=va.w;
                    v[4]=vb.x; v[5]=vb.y; v[6]=vb.z; v[7]=vb.w;
                }
            }
            unsigned outw[4];
            #pragma unroll
            for (int s = 0; s < 4; ++s) {
                __nv_bfloat162 mb = __floats2bfloat162_rn(v[2*s], v[2*s+1]);
                outw[s] = *(unsigned*)&mb;
            }
            *(uint4*)(As + row * 136 + j) = *(uint4*)outw;
        }
        __syncthreads();

        float acc[8][4] = {};
        #pragma unroll
        for (int ks = 0; ks < 8; ++ks) {
            uint4 a = ldsm4(alane + ks * 32);
            #pragma unroll
            for (int pp = 0; pp < 4; ++pp) {
                uint4 b = *(const uint4*)(Wg + (((h * 8 + ks) * 4 + pp) << 7) + lane * 4);
                mma16(acc[2 * pp],     a, b.x, b.y);
                mma16(acc[2 * pp + 1], a, b.z, b.w);
            }
        }
        int r0 = base + q * 16 + g2;
        #pragma unroll
        for (int nt = 0; nt < 8; ++nt) {
            int col = h * 64 + 8 * nt + 2 * tg;
            if (r0 < n) {
                __nv_bfloat162 pv = __floats2bfloat162_rn(acc[nt][0], acc[nt][1]);
                g_pb[(size_t)r0 * 64 + (col >> 1)] = *(unsigned*)&pv;
            }
            if (r0 + 8 < n) {
                __nv_bfloat162 pv = __floats2bfloat162_rn(acc[nt][2], acc[nt][3]);
                g_pb[(size_t)(r0 + 8) * 64 + (col >> 1)] = *(unsigned*)&pv;
            }
        }
    }
}

// ---------------- edge kernel: global B fragments, bf16 epilogue --------------
__global__ void __launch_bounds__(NT, 4) k_edge(
    const float* __restrict__ Wtail,
    const float* __restrict__ b1a,
    int wl, const float* __restrict__ b1b,
    int E, int ntiles)
{
    extern __shared__ float smem[];
    __nv_bfloat16* As = (__nv_bfloat16*)smem;            // 64 x 136 bf16 (4352 w)
    unsigned* Dsb = (unsigned*)As;                       // 64 x 68 words overlay
    float* wt0p = (float*)(As + 64 * 136);               // 144
    float* wt1p = wt0p + 144;                            // 144
    float* bsp  = wt1p + 144;                            // 144
    float* b2s  = bsp + 144;                             // 128
    float* eas  = b2s + 128;                             // 128
    int*   sd   = (int*)(eas + 128);                     // 128

    const int tid  = threadIdx.x;
    const int lane = tid & 31, w = tid >> 5;
    const int q = w & 3, h = w >> 2;
    const int g2 = lane >> 2, tg = lane & 3;

    const unsigned* Wg = g_w1bf + (size_t)wl * 8192;
    if (tid < 128) {
        int c = tid >> 3, s = tid & 7;
        wt0p[c * 9 + s] = Wtail[tid];
        wt1p[c * 9 + s] = Wtail[128 + tid];
        bsp[c * 9 + s]  = b1a[tid];
        b2s[tid] = b1b[tid];
    }
    const unsigned alane = a_lane_addr_bf(As, 272, q, lane);
    const int pc = tid & 15;
    const int pairc = tid & 63, rgrp = tid >> 6;

    int pe_src = 0, pe_dst = -1;
    float2 pe_ea = make_float2(0.f, 0.f);
    if (tid < 64) {
        int e = blockIdx.x * 64 + tid;
        if (e < E) { pe_src = g_esrc[e]; pe_dst = g_edst[e]; pe_ea = g_eea[e]; }
    }

    for (int tile = blockIdx.x; tile < ntiles; tile += gridDim.x) {
        __syncthreads();
        if (tid < 64) {
            sd[tid]      = pe_src;
            sd[64 + tid] = pe_dst;
            eas[2 * tid] = pe_ea.x; eas[2 * tid + 1] = pe_ea.y;
        }
        __syncthreads();
        if (tid < 64) {
            int ntile = tile + gridDim.x;
            int e = ntile * 64 + tid;
            pe_src = 0; pe_dst = -1; pe_ea = make_float2(0.f, 0.f);
            if (ntile < ntiles && e < E) {
                pe_src = g_esrc[e]; pe_dst = g_edst[e]; pe_ea = g_eea[e];
            }
        }

        for (int wi = tid; wi < 1024; wi += NT) {
            int row = wi >> 4, j = pc * 8;
            uint4 p8 = ((const uint4*)(g_pb + (size_t)sd[row] * 64))[pc];
            float ev0 = eas[2 * row], ev1 = eas[2 * row + 1];
            unsigned pw[4] = {p8.x, p8.y, p8.z, p8.w};
            unsigned outw[4];
            #pragma unroll
            for (int s = 0; s < 4; ++s) {
                float2 pf = __bfloat1622float2(*(__nv_bfloat162*)&pw[s]);
                float m0 = fmaf(ev0, wt0p[pc*9 + 2*s],
                                fmaf(ev1, wt1p[pc*9 + 2*s],   pf.x + bsp[pc*9 + 2*s]));
                float m1 = fmaf(ev0, wt0p[pc*9 + 2*s+1],
                                fmaf(ev1, wt1p[pc*9 + 2*s+1], pf.y + bsp[pc*9 + 2*s+1]));
                __nv_bfloat162 mb = __floats2bfloat162_rn(fmaxf(m0, 0.f), fmaxf(m1, 0.f));
                outw[s] = *(unsigned*)&mb;
            }
            *(uint4*)(As + row * 136 + j) = *(uint4*)outw;
        }
        __syncthreads();

        float acc[8][4] = {};
        #pragma unroll
        for (int ks = 0; ks < 8; ++ks) {
            uint4 a = ldsm4(alane + ks * 32);
            #pragma unroll
            for (int pp = 0; pp < 4; ++pp) {
                uint4 b = *(const uint4*)(Wg + (((h * 8 + ks) * 4 + pp) << 7) + lane * 4);
                mma16(acc[2 * pp],     a, b.x, b.y);
                mma16(acc[2 * pp + 1], a, b.z, b.w);
            }
        }
        __syncthreads();   // ldsm reads done -> Dsb may overwrite As

        #pragma unroll
        for (int nt = 0; nt < 8; ++nt) {
            int col = h * 64 + 8 * nt + 2 * tg;
            float bb0 = b2s[col], bb1 = b2s[col + 1];
            __nv_bfloat162 d0 = __floats2bfloat162_rn(
                fmaxf(acc[nt][0] + bb0, 0.f), fmaxf(acc[nt][1] + bb1, 0.f));
            __nv_bfloat162 d1 = __floats2bfloat162_rn(
                fmaxf(acc[nt][2] + bb0, 0.f), fmaxf(acc[nt][3] + bb1, 0.f));
            Dsb[(q * 16 + g2) * 68 + (col >> 1)]       = *(unsigned*)&d0;
            Dsb[(q * 16 + g2 + 8) * 68 + (col >> 1)]   = *(unsigned*)&d1;
        }
        __syncthreads();

        {
            int gr = rgrp * 16;
            float2 sv = make_float2(0.f, 0.f);
            int cur = sd[64 + gr];
            #pragma unroll
            for (int r = 0; r < 16; ++r) {
                int dd = sd[64 + gr + r];
                unsigned uw = Dsb[(gr + r) * 68 + pairc];
                float2 v = __bfloat1622float2(*(__nv_bfloat162*)&uw);
                if (dd != cur) {
                    if (cur >= 0)
                        asm volatile("red.global.add.v2.f32 [%0], {%1,%2};"
                                     :: "l"(g_agg + (size_t)cur * HH + pairc * 2),
                                        "f"(sv.x), "f"(sv.y) : "memory");
                    sv = make_float2(0.f, 0.f);
                    cur = dd;
                }
                sv.x += v.x; sv.y += v.y;
            }
            if (cur >= 0)
                asm volatile("red.global.add.v2.f32 [%0], {%1,%2};"
                             :: "l"(g_agg + (size_t)cur * HH + pairc * 2),
                                "f"(sv.x), "f"(sv.y) : "memory");
        }
    }
}

// ---------------- update1: global B fragments (K=256) -------------------------
__global__ void __launch_bounds__(NT, 3) k_update1(
    const float* __restrict__ b2a,
    int l, int n, int ntiles, int zero_agg)
{
    extern __shared__ float smem[];
    __nv_bfloat16* As = (__nv_bfloat16*)smem;            // 64 x 264 bf16 (8448 w)
    float* sinv = (float*)(As + 64 * 264);               // 64
    const int tid  = threadIdx.x;
    const int lane = tid & 31, w = tid >> 5;
    const int q = w & 3, h = w >> 2;
    const int g = lane >> 2, tg = lane & 3;

    const unsigned* Wg = g_w2af + (size_t)l * 16384;
    float bv[16];
    #pragma unroll
    for (int nt = 0; nt < 8; ++nt) {
        int col = h * 64 + 8 * nt + 2 * tg;
        bv[2 * nt]     = b2a[col];
        bv[2 * nt + 1] = b2a[col + 1];
    }
    const unsigned alane = a_lane_addr_bf(As, 528, q, lane);
    const int cu = tid & 31;

    for (int tile = blockIdx.x; tile < ntiles; tile += gridDim.x) {
        const int base = tile * 64;
        __syncthreads();
        if (tid < 64) {
            int node = base + tid;
            sinv[tid] = (node < n) ? 1.f / fmaxf((float)g_cnt[node], 1.f) : 0.f;
        }
        __syncthreads();

        for (int wi = tid; wi < 2048; wi += NT) {
            int row = wi >> 5, j = cu * 8;
            int node = base + row;
            float v[8] = {0,0,0,0,0,0,0,0};
            if (node < n) {
                if (cu < 16) {
                    float4 va = *(const float4*)(g_h + (size_t)node * HH + j);
                    float4 vb = *(const float4*)(g_h + (size_t)node * HH + j + 4);
                    v[0]=va.x; v[1]=va.y; v[2]=va.z; v[3]=va.w;
                    v[4]=vb.x; v[5]=vb.y; v[6]=vb.z; v[7]=vb.w;
                } else {
                    int ja = j - 128;
                    float4 va = *(const float4*)(g_agg + (size_t)node * HH + ja);
                    float4 vb = *(const float4*)(g_agg + (size_t)node * HH + ja + 4);
                    float iv = sinv[row];
                    v[0]=va.x*iv; v[1]=va.y*iv; v[2]=va.z*iv; v[3]=va.w*iv;
                    v[4]=vb.x*iv; v[5]=vb.y*iv; v[6]=vb.z*iv; v[7]=vb.w*iv;
                    if (zero_agg) {
                        *(float4*)(g_agg + (size_t)node * HH + ja)     = make_float4(0,0,0,0);
                        *(float4*)(g_agg + (size_t)node * HH + ja + 4) = make_float4(0,0,0,0);
                    }
                }
            }
            unsigned outw[4];
            #pragma unroll
            for (int s = 0; s < 4; ++s) {
                __nv_bfloat162 mb = __floats2bfloat162_rn(v[2*s], v[2*s+1]);
                outw[s] = *(unsigned*)&mb;
            }
            *(uint4*)(As + row * 264 + j) = *(uint4*)outw;
        }
        __syncthreads();

        float acc[8][4] = {};
        #pragma unroll
        for (int ks = 0; ks < 16; ++ks) {
            uint4 a = ldsm4(alane + ks * 32);
            #pragma unroll
            for (int pp = 0; pp < 4; ++pp) {
                uint4 b = *(const uint4*)(Wg + (((h * 16 + ks) * 4 + pp) << 7) + lane * 4);
                mma16(acc[2 * pp],     a, b.x, b.y);
                mma16(acc[2 * pp + 1], a, b.z, b.w);
            }
        }

        int r0 = base + q * 16 + g;
        #pragma unroll
        for (int nt = 0; nt < 8; ++nt) {
            int col = h * 64 + 8 * nt + 2 * tg;
            if (r0 < n) {
                __nv_bfloat162 uv = __floats2bfloat162_rn(
                    fmaxf(acc[nt][0] + bv[2 * nt], 0.f),
                    fmaxf(acc[nt][1] + bv[2 * nt + 1], 0.f));
                g_ub[(size_t)r0 * 64 + (col >> 1)] = *(unsigned*)&uv;
            }
            if (r0 + 8 < n) {
                __nv_bfloat162 uv = __floats2bfloat162_rn(
                    fmaxf(acc[nt][2] + bv[2 * nt], 0.f),
                    fmaxf(acc[nt][3] + bv[2 * nt + 1], 0.f));
                g_ub[(size_t)(r0 + 8) * 64 + (col >> 1)] = *(unsigned*)&uv;
            }
        }
    }
}

// ---------------- update2: global B fragments, 4 blk/SM -----------------------
__global__ void __launch_bounds__(NT, 4) k_update2(
    const float* __restrict__ b2b,
    int l, int n, int ntiles)
{
    extern __shared__ float smem[];
    // union region (8448 w): As (bf16 64x136, first 4352 w) then Dr (f32 64x132)
    __nv_bfloat16* As = (__nv_bfloat16*)smem;
    float* Dr = smem;
    const int tid  = threadIdx.x;
    const int lane = tid & 31, w = tid >> 5;
    const int q = w & 3, h = w >> 2;
    const int g = lane >> 2, tg = lane & 3;

    const unsigned* Wg = g_w2bf + (size_t)l * 8192;
    float bv[16];
    #pragma unroll
    for (int nt = 0; nt < 8; ++nt) {
        int col = h * 64 + 8 * nt + 2 * tg;
        bv[2 * nt]     = b2b[col];
        bv[2 * nt + 1] = b2b[col + 1];
    }
    const unsigned alane = a_lane_addr_bf(As, 272, q, lane);
    const int pc = tid & 15;

    for (int tile = blockIdx.x; tile < ntiles; tile += gridDim.x) {
        const int base = tile * 64;
        __syncthreads();
        for (int wi = tid; wi < 1024; wi += NT) {
            int row = wi >> 4;
            int node = base + row;
            uint4 u = make_uint4(0, 0, 0, 0);
            if (node < n) u = ((const uint4*)(g_ub + (size_t)node * 64))[pc];
            *(uint4*)(As + row * 136 + pc * 8) = u;
        }
        __syncthreads();

        float acc[8][4] = {};
        #pragma unroll
        for (int ks = 0; ks < 8; ++ks) {
            uint4 a = ldsm4(alane + ks * 32);
            #pragma unroll
            for (int pp = 0; pp < 4; ++pp) {
                uint4 b = *(const uint4*)(Wg + (((h * 8 + ks) * 4 + pp) << 7) + lane * 4);
                mma16(acc[2 * pp],     a, b.x, b.y);
                mma16(acc[2 * pp + 1], a, b.z, b.w);
            }
        }
        __syncthreads();   // ldsm done -> Dr may overwrite As region

        int r0 = base + q * 16 + g;
        #pragma unroll
        for (int nt = 0; nt < 8; ++nt) {
            int col = h * 64 + 8 * nt + 2 * tg;
            float2 rv0 = make_float2(0.f, 0.f), rv1 = make_float2(0.f, 0.f);
            if (r0 < n) {
                float2 hv = *(const float2*)(g_h + (size_t)r0 * HH + col);
                rv0.x = hv.x + 1.f / (1.f + expf(-(acc[nt][0] + bv[2 * nt])));
                rv0.y = hv.y + 1.f / (1.f + expf(-(acc[nt][1] + bv[2 * nt + 1])));
            }
            if (r0 + 8 < n) {
                float2 hv = *(const float2*)(g_h + (size_t)(r0 + 8) * HH + col);
                rv1.x = hv.x + 1.f / (1.f + expf(-(acc[nt][2] + bv[2 * nt])));
                rv1.y = hv.y + 1.f / (1.f + expf(-(acc[nt][3] + bv[2 * nt + 1])));
            }
            *(float2*)(Dr + (q * 16 + g) * 132 + col)     = rv0;
            *(float2*)(Dr + (q * 16 + g + 8) * 132 + col) = rv1;
        }
        __syncthreads();

        for (int wi = tid; wi < 2048; wi += NT) {
            int row = wi >> 5, j = (wi & 31) << 2;
            if (base + row < n) {
                float4 v = *(const float4*)(Dr + row * 132 + j);
                *(float4*)(g_r + (size_t)(base + row) * HH + j) = v;
            }
        }
        {
            int c = tid & 127, half = tid >> 7;
            float s = 0.f, s2 = 0.f;
            #pragma unroll 8
            for (int r = half * 32; r < half * 32 + 32; ++r) {
                float v = Dr[r * 132 + c];
                s += v; s2 += v * v;
            }
            atomicAdd(&g_sum[l * HH + c], s);
            atomicAdd(&g_sq[l * HH + c],  s2);
        }
    }
}

// ---------------- final MLP (tf32 mma) with fused BN --------------------------
__global__ void __launch_bounds__(NT, 2) k_final(
    const float* __restrict__ Wfp, const float* __restrict__ bf,
    const float* __restrict__ Wo, const float* __restrict__ bo,
    const float* __restrict__ gamma, const float* __restrict__ beta,
    int bnl, float* __restrict__ out, int n, int ntiles)
{
    extern __shared__ float smem[];
    float* Wf = smem;               // 16896
    float* As = Wf + 16896;         // 64*132
    float* sc = As + 8448;          // 128
    float* sh = sc + 128;           // 128
    const int tid  = threadIdx.x;
    const int lane = tid & 31, w = tid >> 5;
    const int q = w & 3, h = w >> 2;
    const int g = lane >> 2, tg = lane & 3;

    stage_w_frag(Wf, Wfp, 16, tid);
    if (tid < 128) {
        float invn = 1.f / (float)n;
        float mu  = g_sum[bnl * HH + tid] * invn;
        float var = g_sq[bnl * HH + tid] * invn - mu * mu;
        float s = gamma[tid] * rsqrtf(var + EPSBN);
        sc[tid] = s; sh[tid] = beta[tid] - mu * s;
    }
    float bv[16];
    #pragma unroll
    for (int nt = 0; nt < 8; ++nt) {
        int col = h * 64 + 8 * nt + 2 * tg;
        bv[2 * nt]     = bf[col];
        bv[2 * nt + 1] = bf[col + 1];
    }
    const unsigned alane = a_lane_addr(As, 132, q, lane);

    for (int tile = blockIdx.x; tile < ntiles; tile += gridDim.x) {
        const int base = tile * 64;
        __syncthreads();
        for (int wi = tid; wi < 2048; wi += NT) {
            int row = wi >> 5, j = (wi & 31) << 2;
            float4 v = make_float4(0.f, 0.f, 0.f, 0.f);
            if (base + row < n) {
                v = *(const float4*)(g_r + (size_t)(base + row) * HH + j);
                v.x = v.x * sc[j + 0] + sh[j + 0];
                v.y = v.y * sc[j + 1] + sh[j + 1];
                v.z = v.z * sc[j + 2] + sh[j + 2];
                v.w = v.w * sc[j + 3] + sh[j + 3];
            }
            uint4 st = make_uint4(f2tf32(v.x), f2tf32(v.y), f2tf32(v.z), f2tf32(v.w));
            *(uint4*)(As + row * 132 + j) = st;
        }
        __syncthreads();

        float acc[8][4] = {};
        #pragma unroll
        for (int ks = 0; ks < 16; ++ks) {
            uint4 a = ldsm4(alane + (ks << 5));
            #pragma unroll
            for (int p = 0; p < 4; ++p) {
                uint4 b = *(const uint4*)(Wf + ((h * 16 + ks) * 4 + p) * 132 + lane * 4);
                mma8(acc[2 * p],     a, b.x, b.y);
                mma8(acc[2 * p + 1], a, b.z, b.w);
            }
        }
        __syncthreads();   // ldsm done -> reuse As as f tile

        #pragma unroll
        for (int nt = 0; nt < 8; ++nt) {
            int col = h * 64 + 8 * nt + 2 * tg;
            *(float2*)(As + (q * 16 + g) * 132 + col) =
                make_float2(fmaxf(acc[nt][0] + bv[2 * nt], 0.f),
                            fmaxf(acc[nt][1] + bv[2 * nt + 1], 0.f));
            *(float2*)(As + (q * 16 + g + 8) * 132 + col) =
                make_float2(fmaxf(acc[nt][2] + bv[2 * nt], 0.f),
                            fmaxf(acc[nt][3] + bv[2 * nt + 1], 0.f));
        }
        __syncthreads();

        const int rw = tid >> 5;
        #pragma unroll
        for (int rr = 0; rr < 8; ++rr) {
            int row = rw * 8 + rr;
            float sAcc = 0.f;
            #pragma unroll
            for (int qq = 0; qq < 4; ++qq)
                sAcc += As[row * 132 + lane + 32 * qq] * Wo[lane + 32 * qq];
            #pragma unroll
            for (int off = 16; off; off >>= 1)
                sAcc += __shfl_xor_sync(0xffffffffu, sAcc, off);
            if (lane == 0 && base + row < n)
                out[base + row] = 1.f / (1.f + expf(-(sAcc + bo[0])));
        }
    }
}

// ---------------- launcher -----------------------------------------------------
extern "C" void kernel_launch(void* const* d_in, const int* in_sizes, int n_in,
                              void* d_out, int out_size)
{
    const float* x    = (const float*)d_in[0];
    const float* ea   = (const float*)d_in[1];
    const int*   ei   = (const int*)  d_in[2];
    const float* W0   = (const float*)d_in[4];
    const float* b0   = (const float*)d_in[5];
    const float* W1   = (const float*)d_in[6];
    const float* b1   = (const float*)d_in[7];
    const float* W1a  = (const float*)d_in[8];
    const float* b1a  = (const float*)d_in[9];
    const float* W1b  = (const float*)d_in[10];
    const float* b1b  = (const float*)d_in[11];
    const float* W2a  = (const float*)d_in[12];
    const float* b2a  = (const float*)d_in[13];
    const float* W2b  = (const float*)d_in[14];
    const float* b2b  = (const float*)d_in[15];
    const float* gam  = (const float*)d_in[16];
    const float* bet  = (const float*)d_in[17];
    const float* Wf   = (const float*)d_in[18];
    const float* bf   = (const float*)d_in[19];
    const float* Wo   = (const float*)d_in[20];
    const float* bo   = (const float*)d_in[21];
    float* out = (float*)d_out;

    const int n = in_sizes[0] / 2;
    const int E = in_sizes[2] / 2;
    const int* srcp = ei;
    const int* dstp = ei + E;

    const int ntiles_n = (n + 63) / 64;
    const int ntiles_e = (E + 63) / 64;
    const int nscan    = (n + 1023) / 1024;
    const int gPers2   = 296;
    const int gPers3   = 444;
    const int gPers4   = 592;

    const size_t SM_IN = (size_t)(16896 + 8448 + 256 + 128 + 128) * 4;
    const size_t SM_P  = (size_t)(4352 + 288) * 4;                   // 18560
    const size_t SM_E  = (size_t)(4352 + 432 + 128 + 128 + 128) * 4; // 20672
    const size_t SM_U1 = (size_t)(8448 + 64) * 4;                    // 34048
    const size_t SM_U2 = (size_t)(8448) * 4;                         // 33792
    const size_t SM_F  = (size_t)(16896 + 8448 + 256) * 4;

    cudaFuncSetAttribute(k_input, cudaFuncAttributeMaxDynamicSharedMemorySize, (int)SM_IN);
    cudaFuncSetAttribute(k_edge, cudaFuncAttributeMaxDynamicSharedMemorySize, (int)SM_E);
    cudaFuncSetAttribute(k_precompute, cudaFuncAttributeMaxDynamicSharedMemorySize, (int)SM_P);
    cudaFuncSetAttribute(k_update1, cudaFuncAttributeMaxDynamicSharedMemorySize, (int)SM_U1);
    cudaFuncSetAttribute(k_update2, cudaFuncAttributeMaxDynamicSharedMemorySize, (int)SM_U2);
    cudaFuncSetAttribute(k_final, cudaFuncAttributeMaxDynamicSharedMemorySize, (int)SM_F);

    k_zero<<<1024, 256>>>(n);
    k_wprep<<<(LL * 40960 + 255) / 256, 256>>>(W1a, W1b, W2a, W2b);
    k_input<<<gPers2, NT, SM_IN>>>(x, W0, b0, W1, b1, dstp, E, n, ntiles_n);
    k_scanA<<<nscan, 1024>>>(n);
    k_scanB<<<1, 128>>>(nscan, n);
    k_scanC<<<(n + 255) / 256, 256>>>(n);
    k_sort<<<(E + 255) / 256, 256>>>(srcp, dstp, ea, E);

    for (int l = 0; l < LL; ++l) {
        const float* W1a_l  = W1a + (size_t)l * 130 * 128;
        const float* W1a_t  = W1a_l + 128 * 128;
        const float* b1a_l  = b1a + (size_t)l * 128;
        const float* b1b_l  = b1b + (size_t)l * 128;
        const float* b2a_l  = b2a + (size_t)l * 128;
        const float* b2b_l  = b2b + (size_t)l * 128;
        const float* gam_p  = (l > 0) ? gam + (size_t)(l - 1) * 128 : gam;
        const float* bet_p  = (l > 0) ? bet + (size_t)(l - 1) * 128 : bet;

        k_precompute<<<gPers4, NT, SM_P>>>(gam_p, bet_p, l, l - 1, n, ntiles_n);
        k_edge<<<gPers4, NT, SM_E>>>(W1a_t, b1a_l, l, b1b_l, E, ntiles_e);
        k_update1<<<gPers3, NT, SM_U1>>>(b2a_l, l, n, ntiles_n,
                                         (l < LL - 1) ? 1 : 0);
        k_update2<<<gPers4, NT, SM_U2>>>(b2b_l, l, n, ntiles_n);
    }

    k_final<<<gPers2, NT, SM_F>>>(Wf, bf, Wo, bo,
                                  gam + (size_t)(LL - 1) * 128,
                                  bet + (size_t)(LL - 1) * 128,
                                  LL - 1, out, n, ntiles_n);
}

// round 17
// speedup vs baseline: 1.0095x; 1.0095x over previous
#include <cuda_runtime.h>
#include <cuda_bf16.h>
#include <math.h>
#include <stdint.h>

#define NN 50000
#define EE 800000
#define HH 128
#define LL 3
#define NT 256
#define EPSBN 1e-5f

// ---------------- scratch ---------------------------------------------------
__device__ float    g_h[NN * HH];
__device__ unsigned g_pb[NN * 64];     // P in bf16x2
__device__ float    g_agg[NN * HH];
__device__ unsigned g_ub[NN * 64];     // U in bf16x2
__device__ float    g_r[NN * HH];
__device__ int      g_cnt[NN];
__device__ int      g_fill[NN];
__device__ int      g_eoff[NN + 1];
__device__ int      g_bsum[128];
__device__ int      g_esrc[EE];
__device__ int      g_edst[EE];
__device__ float2   g_eea[EE];
__device__ float    g_sum[LL * HH];
__device__ float    g_sq[LL * HH];
// bf16 B-fragment tables (global-resident, stride 128/group)
__device__ unsigned g_w1af[LL * 8192];    // W1a top (K=128)
__device__ unsigned g_w1bf[LL * 8192];    // W1b     (K=128)
__device__ unsigned g_w2af[LL * 16384];   // W2a     (K=256)
__device__ unsigned g_w2bf[LL * 8192];    // W2b     (K=128)

// ---------------- mma / ldmatrix helpers -------------------------------------
__device__ __forceinline__ unsigned f2tf32(float f) {
    unsigned u;
    asm("cvt.rna.tf32.f32 %0, %1;" : "=r"(u) : "f"(f));
    return u;
}
__device__ __forceinline__ void mma8(float acc[4], const uint4& a,
                                     unsigned b0, unsigned b1) {
    asm volatile(
        "mma.sync.aligned.m16n8k8.row.col.f32.tf32.tf32.f32 "
        "{%0,%1,%2,%3},{%4,%5,%6,%7},{%8,%9},{%0,%1,%2,%3};\n"
        : "+f"(acc[0]), "+f"(acc[1]), "+f"(acc[2]), "+f"(acc[3])
        : "r"(a.x), "r"(a.y), "r"(a.z), "r"(a.w), "r"(b0), "r"(b1));
}
__device__ __forceinline__ void mma16(float acc[4], const uint4& a,
                                      unsigned b0, unsigned b1) {
    asm volatile(
        "mma.sync.aligned.m16n8k16.row.col.f32.bf16.bf16.f32 "
        "{%0,%1,%2,%3},{%4,%5,%6,%7},{%8,%9},{%0,%1,%2,%3};\n"
        : "+f"(acc[0]), "+f"(acc[1]), "+f"(acc[2]), "+f"(acc[3])
        : "r"(a.x), "r"(a.y), "r"(a.z), "r"(a.w), "r"(b0), "r"(b1));
}
__device__ __forceinline__ uint4 ldsm4(unsigned addr) {
    uint4 r;
    asm volatile("ldmatrix.sync.aligned.m8n8.x4.shared.b16 {%0,%1,%2,%3}, [%4];"
        : "=r"(r.x), "=r"(r.y), "=r"(r.z), "=r"(r.w) : "r"(addr));
    return r;
}
// tf32 A-frag lane address (fp32 row-major, lda floats)
__device__ __forceinline__ unsigned a_lane_addr(const float* As, int lda,
                                                int q, int lane) {
    return (unsigned)__cvta_generic_to_shared(As)
         + ((((q * 16 + (lane & 15)) * lda) + 4 * (lane >> 4)) << 2);
}
// bf16 row-major A tile, stride in BYTES
__device__ __forceinline__ unsigned a_lane_addr_bf(const void* As, int strideB,
                                                   int q, int lane) {
    return (unsigned)__cvta_generic_to_shared(As)
         + (q * 16 + (lane & 7) + 8 * ((lane >> 3) & 1)) * strideB
         + (lane >> 4) * 16;
}

// KxN(128) fp32 weight -> tf32 B fragments (smem path, k_input/k_final only)
__device__ __forceinline__ void stage_w_frag(float* Wf, const float* __restrict__ Wg,
                                             int KS, int tid)
{
    const int total = 2 * KS * 4 * 132;
    for (int i = tid; i < total; i += NT) {
        int grp = i / 132, off = i % 132;
        if (off < 128) {
            int s = off & 3, t = off >> 2;
            int gg = t >> 2, tt = t & 3;
            int hh = grp / (KS * 4);
            int rem = grp - hh * (KS * 4);
            int ks = rem >> 2, p = rem & 3;
            int k = 8 * ks + tt + ((s & 1) ? 4 : 0);
            int n = hh * 64 + 16 * p + gg + ((s >= 2) ? 8 : 0);
            Wf[i] = __uint_as_float(f2tf32(Wg[(size_t)k * 128 + n]));
        }
    }
}

// ---------------- one-shot init: weight fragments + zeroing ------------------
__device__ __forceinline__ unsigned frag_val(const float* __restrict__ Wg,
                                             int KS, int idx)
{
    int grp = idx >> 7, off = idx & 127;
    int s = off & 3, lane = off >> 2;
    int g = lane >> 2, t = lane & 3;
    int hh = grp / (KS * 4);
    int rem = grp - hh * (KS * 4);
    int ks = rem >> 2, pp = rem & 3;
    int p = 2 * pp + (s >> 1);
    int bsel = s & 1;
    int n = hh * 64 + p * 8 + g;
    int k0 = ks * 16 + 2 * t + 8 * bsel;
    __nv_bfloat162 v = __floats2bfloat162_rn(Wg[(size_t)k0 * 128 + n],
                                             Wg[(size_t)(k0 + 1) * 128 + n]);
    return *(unsigned*)&v;
}
__global__ void k_init(const float* __restrict__ W1a,
                       const float* __restrict__ W1b,
                       const float* __restrict__ W2a,
                       const float* __restrict__ W2b, int n)
{
    int i = blockIdx.x * blockDim.x + threadIdx.x;
    if (i < LL * 40960) {
        int l = i / 40960, r = i - l * 40960;
        if (r < 8192)
            g_w1af[l * 8192 + r]  = frag_val(W1a + (size_t)l * 130 * 128, 8, r);
        else if (r < 16384)
            g_w1bf[l * 8192 + (r - 8192)] = frag_val(W1b + (size_t)l * 128 * 128, 8, r - 8192);
        else if (r < 32768)
            g_w2af[l * 16384 + (r - 16384)] = frag_val(W2a + (size_t)l * 256 * 128, 16, r - 16384);
        else
            g_w2bf[l * 8192 + (r - 32768)] = frag_val(W2b + (size_t)l * 128 * 128, 8, r - 32768);
    }
    int total = n * HH;
    for (int j = i; j < total; j += gridDim.x * blockDim.x) {
        g_agg[j] = 0.f;
        if (j < n) { g_cnt[j] = 0; g_fill[j] = 0; }
        if (j < LL * HH) { g_sum[j] = 0.f; g_sq[j] = 0.f; }
    }
}

// ---------------- fast two-level scan ----------------------------------------
__global__ void k_scanA(int n)
{
    __shared__ int buf[1024];
    const int tid = threadIdx.x;
    const int base = blockIdx.x * 1024;
    int v = (base + tid < n) ? g_cnt[base + tid] : 0;
    buf[tid] = v;
    __syncthreads();
    for (int off = 1; off < 1024; off <<= 1) {
        int t = (tid >= off) ? buf[tid - off] : 0;
        __syncthreads();
        buf[tid] += t;
        __syncthreads();
    }
    if (base + tid < n) g_eoff[base + tid] = buf[tid];
    if (tid == 1023) g_bsum[blockIdx.x] = buf[1023];
}
__global__ void k_scanB(int nb, int n)
{
    __shared__ int buf[128];
    const int tid = threadIdx.x;
    int v = (tid < nb) ? g_bsum[tid] : 0;
    buf[tid] = v;
    __syncthreads();
    for (int off = 1; off < 128; off <<= 1) {
        int t = (tid >= off) ? buf[tid - off] : 0;
        __syncthreads();
        buf[tid] += t;
        __syncthreads();
    }
    if (tid < nb) g_bsum[tid] = buf[tid] - v;
    if (tid == 127) g_eoff[n] = buf[127];
}
__global__ void k_scanC(int n)
{
    int i = blockIdx.x * blockDim.x + threadIdx.x;
    if (i < n) g_eoff[i] = g_eoff[i] - g_cnt[i] + g_bsum[i >> 10];
}

// ---------------- counting-sort scatter --------------------------------------
__global__ void k_sort(const int* __restrict__ src, const int* __restrict__ dst,
                       const float* __restrict__ ea, int E)
{
    int e = blockIdx.x * blockDim.x + threadIdx.x;
    if (e < E) {
        int d = dst[e];
        float2 ev = *(const float2*)(ea + 2 * (size_t)e);
        int slot = g_eoff[d] + atomicAdd(&g_fill[d], 1);
        g_esrc[slot] = src[e];
        g_edst[slot] = d;
        g_eea[slot] = ev;
    }
}

// ---------------- input MLP (tf32 mma) + degree count ------------------------
__global__ void __launch_bounds__(NT, 2) k_input(
    const float* __restrict__ x,
    const float* __restrict__ W0, const float* __restrict__ b0,
    const float* __restrict__ W1, const float* __restrict__ b1,
    const int* __restrict__ dst, int E, int n, int ntiles)
{
    extern __shared__ float smem[];
    float* Wf  = smem;              // 16896
    float* As  = Wf + 16896;        // 64*132
    float* w0s = As + 8448;         // 256
    float* b0s = w0s + 256;         // 128
    float* xs  = b0s + 128;         // 128
    const int tid  = threadIdx.x;
    const int lane = tid & 31, w = tid >> 5;
    const int q = w & 3, h = w >> 2;
    const int g = lane >> 2, tg = lane & 3;

    for (int e = blockIdx.x * blockDim.x + tid; e < E; e += gridDim.x * blockDim.x)
        atomicAdd(&g_cnt[dst[e]], 1);

    stage_w_frag(Wf, W1, 16, tid);
    for (int t = tid; t < 256; t += NT) w0s[t] = W0[t];
    if (tid < 128) b0s[tid] = b0[tid];
    float bv[16];
    #pragma unroll
    for (int nt = 0; nt < 8; ++nt) {
        int col = h * 64 + 8 * nt + 2 * tg;
        bv[2 * nt]     = b1[col];
        bv[2 * nt + 1] = b1[col + 1];
    }
    const unsigned alane = a_lane_addr(As, 132, q, lane);

    for (int tile = blockIdx.x; tile < ntiles; tile += gridDim.x) {
        const int base = tile * 64;
        __syncthreads();
        if (tid < 128)
            xs[tid] = (base + (tid >> 1) < n) ? x[(size_t)base * 2 + tid] : 0.f;
        __syncthreads();

        for (int wi = tid; wi < 2048; wi += NT) {
            int row = wi >> 5, j = (wi & 31) << 2;
            float x0 = xs[row * 2], x1 = xs[row * 2 + 1];
            uint4 st;
            st.x = f2tf32(fmaxf(fmaf(x0, w0s[j+0], fmaf(x1, w0s[128+j+0], b0s[j+0])), 0.f));
            st.y = f2tf32(fmaxf(fmaf(x0, w0s[j+1], fmaf(x1, w0s[128+j+1], b0s[j+1])), 0.f));
            st.z = f2tf32(fmaxf(fmaf(x0, w0s[j+2], fmaf(x1, w0s[128+j+2], b0s[j+2])), 0.f));
            st.w = f2tf32(fmaxf(fmaf(x0, w0s[j+3], fmaf(x1, w0s[128+j+3], b0s[j+3])), 0.f));
            *(uint4*)(As + row * 132 + j) = st;
        }
        __syncthreads();

        float acc[8][4] = {};
        #pragma unroll
        for (int ks = 0; ks < 16; ++ks) {
            uint4 a = ldsm4(alane + (ks << 5));
            #pragma unroll
            for (int p = 0; p < 4; ++p) {
                uint4 b = *(const uint4*)(Wf + ((h * 16 + ks) * 4 + p) * 132 + lane * 4);
                mma8(acc[2 * p],     a, b.x, b.y);
                mma8(acc[2 * p + 1], a, b.z, b.w);
            }
        }

        int r0 = base + q * 16 + g;
        #pragma unroll
        for (int nt = 0; nt < 8; ++nt) {
            int col = h * 64 + 8 * nt + 2 * tg;
            if (r0 < n)
                *(float2*)(g_h + (size_t)r0 * HH + col) =
                    make_float2(fmaxf(acc[nt][0] + bv[2 * nt], 0.f),
                                fmaxf(acc[nt][1] + bv[2 * nt + 1], 0.f));
            if (r0 + 8 < n)
                *(float2*)(g_h + (size_t)(r0 + 8) * HH + col) =
                    make_float2(fmaxf(acc[nt][2] + bv[2 * nt], 0.f),
                                fmaxf(acc[nt][3] + bv[2 * nt + 1], 0.f));
        }
    }
}

// ---------------- P = BN?(h) @ W1a_top : global B fragments -------------------
__global__ void __launch_bounds__(NT, 3) k_precompute(
    const float* __restrict__ gamma, const float* __restrict__ beta,
    int wl, int bnl, int n, int ntiles)
{
    extern __shared__ float smem[];
    __nv_bfloat16* As = (__nv_bfloat16*)smem;            // 64 x 136 bf16 (4352 w)
    float* scp = (float*)(As + 64 * 136);                // 144
    float* shp = scp + 144;                              // 144
    const int tid  = threadIdx.x;
    const int lane = tid & 31, w = tid >> 5;
    const int q = w & 3, h = w >> 2;
    const int g2 = lane >> 2, tg = lane & 3;

    const unsigned* Wg = g_w1af + (size_t)wl * 8192;
    if (tid < 128) {
        int c = tid >> 3, s = tid & 7;
        if (bnl >= 0) {
            float invn = 1.f / (float)n;
            float mu  = g_sum[bnl * HH + tid] * invn;
            float var = g_sq[bnl * HH + tid] * invn - mu * mu;
            float sv = gamma[tid] * rsqrtf(var + EPSBN);
            scp[c * 9 + s] = sv; shp[c * 9 + s] = beta[tid] - mu * sv;
        } else { scp[c * 9 + s] = 1.f; shp[c * 9 + s] = 0.f; }
    }
    const unsigned alane = a_lane_addr_bf(As, 272, q, lane);
    const int pc = tid & 15;

    for (int tile = blockIdx.x; tile < ntiles; tile += gridDim.x) {
        const int base = tile * 64;
        __syncthreads();
        for (int wi = tid; wi < 1024; wi += NT) {
            int row = wi >> 4, j = pc * 8;
            int node = base + row;
            float v[8] = {0,0,0,0,0,0,0,0};
            if (node < n) {
                float4 va, vb;
                if (bnl >= 0) {
                    va = *(const float4*)(g_r + (size_t)node * HH + j);
                    vb = *(const float4*)(g_r + (size_t)node * HH + j + 4);
                    float vv[8] = {va.x,va.y,va.z,va.w,vb.x,vb.y,vb.z,vb.w};
                    #pragma unroll
                    for (int s = 0; s < 8; ++s)
                        v[s] = vv[s] * scp[pc * 9 + s] + shp[pc * 9 + s];
                    *(float4*)(g_h + (size_t)node * HH + j)     = make_float4(v[0],v[1],v[2],v[3]);
                    *(float4*)(g_h + (size_t)node * HH + j + 4) = make_float4(v[4],v[5],v[6],v[7]);
                } else {
                    va = *(const float4*)(g_h + (size_t)node * HH + j);
                    vb = *(const float4*)(g_h + (size_t)node * HH + j + 4);
                    v[0]=va.x; v[1]=va.y; v[2]=va.z; v[3]=va.w;
                    v[4]=vb.x; v[5]=vb.y; v[6]=vb.z; v[7]=vb.w;
                }
            }
            unsigned outw[4];
            #pragma unroll
            for (int s = 0; s < 4; ++s) {
                __nv_bfloat162 mb = __floats2bfloat162_rn(v[2*s], v[2*s+1]);
                outw[s] = *(unsigned*)&mb;
            }
            *(uint4*)(As + row * 136 + j) = *(uint4*)outw;
        }
        __syncthreads();

        float acc[8][4] = {};
        #pragma unroll
        for (int ks = 0; ks < 8; ++ks) {
            uint4 a = ldsm4(alane + ks * 32);
            #pragma unroll
            for (int pp = 0; pp < 4; ++pp) {
                uint4 b = *(const uint4*)(Wg + (((h * 8 + ks) * 4 + pp) << 7) + lane * 4);
                mma16(acc[2 * pp],     a, b.x, b.y);
                mma16(acc[2 * pp + 1], a, b.z, b.w);
            }
        }
        int r0 = base + q * 16 + g2;
        #pragma unroll
        for (int nt = 0; nt < 8; ++nt) {
            int col = h * 64 + 8 * nt + 2 * tg;
            if (r0 < n) {
                __nv_bfloat162 pv = __floats2bfloat162_rn(acc[nt][0], acc[nt][1]);
                g_pb[(size_t)r0 * 64 + (col >> 1)] = *(unsigned*)&pv;
            }
            if (r0 + 8 < n) {
                __nv_bfloat162 pv = __floats2bfloat162_rn(acc[nt][2], acc[nt][3]);
                g_pb[(size_t)(r0 + 8) * 64 + (col >> 1)] = *(unsigned*)&pv;
            }
        }
    }
}

// ---------------- edge kernel: global B fragments, bf16 epilogue --------------
__global__ void __launch_bounds__(NT, 4) k_edge(
    const float* __restrict__ Wtail,
    const float* __restrict__ b1a,
    int wl, const float* __restrict__ b1b,
    int E, int ntiles)
{
    extern __shared__ float smem[];
    __nv_bfloat16* As = (__nv_bfloat16*)smem;            // 64 x 136 bf16 (4352 w)
    unsigned* Dsb = (unsigned*)As;                       // 64 x 68 words overlay
    float* wt0p = (float*)(As + 64 * 136);               // 144
    float* wt1p = wt0p + 144;                            // 144
    float* bsp  = wt1p + 144;                            // 144
    float* b2s  = bsp + 144;                             // 128
    float* eas  = b2s + 128;                             // 128
    int*   sd   = (int*)(eas + 128);                     // 128

    const int tid  = threadIdx.x;
    const int lane = tid & 31, w = tid >> 5;
    const int q = w & 3, h = w >> 2;
    const int g2 = lane >> 2, tg = lane & 3;

    const unsigned* Wg = g_w1bf + (size_t)wl * 8192;
    if (tid < 128) {
        int c = tid >> 3, s = tid & 7;
        wt0p[c * 9 + s] = Wtail[tid];
        wt1p[c * 9 + s] = Wtail[128 + tid];
        bsp[c * 9 + s]  = b1a[tid];
        b2s[tid] = b1b[tid];
    }
    const unsigned alane = a_lane_addr_bf(As, 272, q, lane);
    const int pc = tid & 15;
    const int pairc = tid & 63, rgrp = tid >> 6;

    int pe_src = 0, pe_dst = -1;
    float2 pe_ea = make_float2(0.f, 0.f);
    if (tid < 64) {
        int e = blockIdx.x * 64 + tid;
        if (e < E) { pe_src = g_esrc[e]; pe_dst = g_edst[e]; pe_ea = g_eea[e]; }
    }

    for (int tile = blockIdx.x; tile < ntiles; tile += gridDim.x) {
        __syncthreads();
        if (tid < 64) {
            sd[tid]      = pe_src;
            sd[64 + tid] = pe_dst;
            eas[2 * tid] = pe_ea.x; eas[2 * tid + 1] = pe_ea.y;
        }
        __syncthreads();
        if (tid < 64) {
            int ntile = tile + gridDim.x;
            int e = ntile * 64 + tid;
            pe_src = 0; pe_dst = -1; pe_ea = make_float2(0.f, 0.f);
            if (ntile < ntiles && e < E) {
                pe_src = g_esrc[e]; pe_dst = g_edst[e]; pe_ea = g_eea[e];
            }
        }

        for (int wi = tid; wi < 1024; wi += NT) {
            int row = wi >> 4, j = pc * 8;
            uint4 p8 = ((const uint4*)(g_pb + (size_t)sd[row] * 64))[pc];
            float ev0 = eas[2 * row], ev1 = eas[2 * row + 1];
            unsigned pw[4] = {p8.x, p8.y, p8.z, p8.w};
            unsigned outw[4];
            #pragma unroll
            for (int s = 0; s < 4; ++s) {
                float2 pf = __bfloat1622float2(*(__nv_bfloat162*)&pw[s]);
                float m0 = fmaf(ev0, wt0p[pc*9 + 2*s],
                                fmaf(ev1, wt1p[pc*9 + 2*s],   pf.x + bsp[pc*9 + 2*s]));
                float m1 = fmaf(ev0, wt0p[pc*9 + 2*s+1],
                                fmaf(ev1, wt1p[pc*9 + 2*s+1], pf.y + bsp[pc*9 + 2*s+1]));
                __nv_bfloat162 mb = __floats2bfloat162_rn(fmaxf(m0, 0.f), fmaxf(m1, 0.f));
                outw[s] = *(unsigned*)&mb;
            }
            *(uint4*)(As + row * 136 + j) = *(uint4*)outw;
        }
        __syncthreads();

        float acc[8][4] = {};
        #pragma unroll
        for (int ks = 0; ks < 8; ++ks) {
            uint4 a = ldsm4(alane + ks * 32);
            #pragma unroll
            for (int pp = 0; pp < 4; ++pp) {
                uint4 b = *(const uint4*)(Wg + (((h * 8 + ks) * 4 + pp) << 7) + lane * 4);
                mma16(acc[2 * pp],     a, b.x, b.y);
                mma16(acc[2 * pp + 1], a, b.z, b.w);
            }
        }
        __syncthreads();   // ldsm reads done -> Dsb may overwrite As

        #pragma unroll
        for (int nt = 0; nt < 8; ++nt) {
            int col = h * 64 + 8 * nt + 2 * tg;
            float bb0 = b2s[col], bb1 = b2s[col + 1];
            __nv_bfloat162 d0 = __floats2bfloat162_rn(
                fmaxf(acc[nt][0] + bb0, 0.f), fmaxf(acc[nt][1] + bb1, 0.f));
            __nv_bfloat162 d1 = __floats2bfloat162_rn(
                fmaxf(acc[nt][2] + bb0, 0.f), fmaxf(acc[nt][3] + bb1, 0.f));
            Dsb[(q * 16 + g2) * 68 + (col >> 1)]       = *(unsigned*)&d0;
            Dsb[(q * 16 + g2 + 8) * 68 + (col >> 1)]   = *(unsigned*)&d1;
        }
        __syncthreads();

        {
            int gr = rgrp * 16;
            float2 sv = make_float2(0.f, 0.f);
            int cur = sd[64 + gr];
            #pragma unroll
            for (int r = 0; r < 16; ++r) {
                int dd = sd[64 + gr + r];
                unsigned uw = Dsb[(gr + r) * 68 + pairc];
                float2 v = __bfloat1622float2(*(__nv_bfloat162*)&uw);
                if (dd != cur) {
                    if (cur >= 0)
                        asm volatile("red.global.add.v2.f32 [%0], {%1,%2};"
                                     :: "l"(g_agg + (size_t)cur * HH + pairc * 2),
                                        "f"(sv.x), "f"(sv.y) : "memory");
                    sv = make_float2(0.f, 0.f);
                    cur = dd;
                }
                sv.x += v.x; sv.y += v.y;
            }
            if (cur >= 0)
                asm volatile("red.global.add.v2.f32 [%0], {%1,%2};"
                             :: "l"(g_agg + (size_t)cur * HH + pairc * 2),
                                "f"(sv.x), "f"(sv.y) : "memory");
        }
    }
}

// ---------------- update1: global B fragments (K=256) -------------------------
__global__ void __launch_bounds__(NT, 3) k_update1(
    const float* __restrict__ b2a,
    int l, int n, int ntiles, int zero_agg)
{
    extern __shared__ float smem[];
    __nv_bfloat16* As = (__nv_bfloat16*)smem;            // 64 x 264 bf16 (8448 w)
    float* sinv = (float*)(As + 64 * 264);               // 64
    const int tid  = threadIdx.x;
    const int lane = tid & 31, w = tid >> 5;
    const int q = w & 3, h = w >> 2;
    const int g = lane >> 2, tg = lane & 3;

    const unsigned* Wg = g_w2af + (size_t)l * 16384;
    float bv[16];
    #pragma unroll
    for (int nt = 0; nt < 8; ++nt) {
        int col = h * 64 + 8 * nt + 2 * tg;
        bv[2 * nt]     = b2a[col];
        bv[2 * nt + 1] = b2a[col + 1];
    }
    const unsigned alane = a_lane_addr_bf(As, 528, q, lane);
    const int cu = tid & 31;

    for (int tile = blockIdx.x; tile < ntiles; tile += gridDim.x) {
        const int base = tile * 64;
        __syncthreads();
        if (tid < 64) {
            int node = base + tid;
            sinv[tid] = (node < n) ? 1.f / fmaxf((float)g_cnt[node], 1.f) : 0.f;
        }
        __syncthreads();

        for (int wi = tid; wi < 2048; wi += NT) {
            int row = wi >> 5, j = cu * 8;
            int node = base + row;
            float v[8] = {0,0,0,0,0,0,0,0};
            if (node < n) {
                if (cu < 16) {
                    float4 va = *(const float4*)(g_h + (size_t)node * HH + j);
                    float4 vb = *(const float4*)(g_h + (size_t)node * HH + j + 4);
                    v[0]=va.x; v[1]=va.y; v[2]=va.z; v[3]=va.w;
                    v[4]=vb.x; v[5]=vb.y; v[6]=vb.z; v[7]=vb.w;
                } else {
                    int ja = j - 128;
                    float4 va = *(const float4*)(g_agg + (size_t)node * HH + ja);
                    float4 vb = *(const float4*)(g_agg + (size_t)node * HH + ja + 4);
                    float iv = sinv[row];
                    v[0]=va.x*iv; v[1]=va.y*iv; v[2]=va.z*iv; v[3]=va.w*iv;
                    v[4]=vb.x*iv; v[5]=vb.y*iv; v[6]=vb.z*iv; v[7]=vb.w*iv;
                    if (zero_agg) {
                        *(float4*)(g_agg + (size_t)node * HH + ja)     = make_float4(0,0,0,0);
                        *(float4*)(g_agg + (size_t)node * HH + ja + 4) = make_float4(0,0,0,0);
                    }
                }
            }
            unsigned outw[4];
            #pragma unroll
            for (int s = 0; s < 4; ++s) {
                __nv_bfloat162 mb = __floats2bfloat162_rn(v[2*s], v[2*s+1]);
                outw[s] = *(unsigned*)&mb;
            }
            *(uint4*)(As + row * 264 + j) = *(uint4*)outw;
        }
        __syncthreads();

        float acc[8][4] = {};
        #pragma unroll
        for (int ks = 0; ks < 16; ++ks) {
            uint4 a = ldsm4(alane + ks * 32);
            #pragma unroll
            for (int pp = 0; pp < 4; ++pp) {
                uint4 b = *(const uint4*)(Wg + (((h * 16 + ks) * 4 + pp) << 7) + lane * 4);
                mma16(acc[2 * pp],     a, b.x, b.y);
                mma16(acc[2 * pp + 1], a, b.z, b.w);
            }
        }

        int r0 = base + q * 16 + g;
        #pragma unroll
        for (int nt = 0; nt < 8; ++nt) {
            int col = h * 64 + 8 * nt + 2 * tg;
            if (r0 < n) {
                __nv_bfloat162 uv = __floats2bfloat162_rn(
                    fmaxf(acc[nt][0] + bv[2 * nt], 0.f),
                    fmaxf(acc[nt][1] + bv[2 * nt + 1], 0.f));
                g_ub[(size_t)r0 * 64 + (col >> 1)] = *(unsigned*)&uv;
            }
            if (r0 + 8 < n) {
                __nv_bfloat162 uv = __floats2bfloat162_rn(
                    fmaxf(acc[nt][2] + bv[2 * nt], 0.f),
                    fmaxf(acc[nt][3] + bv[2 * nt + 1], 0.f));
                g_ub[(size_t)(r0 + 8) * 64 + (col >> 1)] = *(unsigned*)&uv;
            }
        }
    }
}

// ---------------- update2: global B fragments ---------------------------------
__global__ void __launch_bounds__(NT, 3) k_update2(
    const float* __restrict__ b2b,
    int l, int n, int ntiles)
{
    extern __shared__ float smem[];
    // union region (8448 w): As (bf16 64x136, first 4352 w) then Dr (f32 64x132)
    __nv_bfloat16* As = (__nv_bfloat16*)smem;
    float* Dr = smem;
    const int tid  = threadIdx.x;
    const int lane = tid & 31, w = tid >> 5;
    const int q = w & 3, h = w >> 2;
    const int g = lane >> 2, tg = lane & 3;

    const unsigned* Wg = g_w2bf + (size_t)l * 8192;
    float bv[16];
    #pragma unroll
    for (int nt = 0; nt < 8; ++nt) {
        int col = h * 64 + 8 * nt + 2 * tg;
        bv[2 * nt]     = b2b[col];
        bv[2 * nt + 1] = b2b[col + 1];
    }
    const unsigned alane = a_lane_addr_bf(As, 272, q, lane);
    const int pc = tid & 15;

    for (int tile = blockIdx.x; tile < ntiles; tile += gridDim.x) {
        const int base = tile * 64;
        __syncthreads();
        for (int wi = tid; wi < 1024; wi += NT) {
            int row = wi >> 4;
            int node = base + row;
            uint4 u = make_uint4(0, 0, 0, 0);
            if (node < n) u = ((const uint4*)(g_ub + (size_t)node * 64))[pc];
            *(uint4*)(As + row * 136 + pc * 8) = u;
        }
        __syncthreads();

        float acc[8][4] = {};
        #pragma unroll
        for (int ks = 0; ks < 8; ++ks) {
            uint4 a = ldsm4(alane + ks * 32);
            #pragma unroll
            for (int pp = 0; pp < 4; ++pp) {
                uint4 b = *(const uint4*)(Wg + (((h * 8 + ks) * 4 + pp) << 7) + lane * 4);
                mma16(acc[2 * pp],     a, b.x, b.y);
                mma16(acc[2 * pp + 1], a, b.z, b.w);
            }
        }
        __syncthreads();   // ldsm done -> Dr may overwrite As region

        int r0 = base + q * 16 + g;
        #pragma unroll
        for (int nt = 0; nt < 8; ++nt) {
            int col = h * 64 + 8 * nt + 2 * tg;
            float2 rv0 = make_float2(0.f, 0.f), rv1 = make_float2(0.f, 0.f);
            if (r0 < n) {
                float2 hv = *(const float2*)(g_h + (size_t)r0 * HH + col);
                rv0.x = hv.x + 1.f / (1.f + expf(-(acc[nt][0] + bv[2 * nt])));
                rv0.y = hv.y + 1.f / (1.f + expf(-(acc[nt][1] + bv[2 * nt + 1])));
            }
            if (r0 + 8 < n) {
                float2 hv = *(const float2*)(g_h + (size_t)(r0 + 8) * HH + col);
                rv1.x = hv.x + 1.f / (1.f + expf(-(acc[nt][2] + bv[2 * nt])));
                rv1.y = hv.y + 1.f / (1.f + expf(-(acc[nt][3] + bv[2 * nt + 1])));
            }
            *(float2*)(Dr + (q * 16 + g) * 132 + col)     = rv0;
            *(float2*)(Dr + (q * 16 + g + 8) * 132 + col) = rv1;
        }
        __syncthreads();

        for (int wi = tid; wi < 2048; wi += NT) {
            int row = wi >> 5, j = (wi & 31) << 2;
            if (base + row < n) {
                float4 v = *(const float4*)(Dr + row * 132 + j);
                *(float4*)(g_r + (size_t)(base + row) * HH + j) = v;
            }
        }
        {
            int c = tid & 127, half = tid >> 7;
            float s = 0.f, s2 = 0.f;
            #pragma unroll 8
            for (int r = half * 32; r < half * 32 + 32; ++r) {
                float v = Dr[r * 132 + c];
                s += v; s2 += v * v;
            }
            atomicAdd(&g_sum[l * HH + c], s);
            atomicAdd(&g_sq[l * HH + c],  s2);
        }
    }
}

// ---------------- final MLP (tf32 mma) with fused BN --------------------------
__global__ void __launch_bounds__(NT, 2) k_final(
    const float* __restrict__ Wfp, const float* __restrict__ bf,
    const float* __restrict__ Wo, const float* __restrict__ bo,
    const float* __restrict__ gamma, const float* __restrict__ beta,
    int bnl, float* __restrict__ out, int n, int ntiles)
{
    extern __shared__ float smem[];
    float* Wf = smem;               // 16896
    float* As = Wf + 16896;         // 64*132
    float* sc = As + 8448;          // 128
    float* sh = sc + 128;           // 128
    const int tid  = threadIdx.x;
    const int lane = tid & 31, w = tid >> 5;
    const int q = w & 3, h = w >> 2;
    const int g = lane >> 2, tg = lane & 3;

    stage_w_frag(Wf, Wfp, 16, tid);
    if (tid < 128) {
        float invn = 1.f / (float)n;
        float mu  = g_sum[bnl * HH + tid] * invn;
        float var = g_sq[bnl * HH + tid] * invn - mu * mu;
        float s = gamma[tid] * rsqrtf(var + EPSBN);
        sc[tid] = s; sh[tid] = beta[tid] - mu * s;
    }
    float bv[16];
    #pragma unroll
    for (int nt = 0; nt < 8; ++nt) {
        int col = h * 64 + 8 * nt + 2 * tg;
        bv[2 * nt]     = bf[col];
        bv[2 * nt + 1] = bf[col + 1];
    }
    const unsigned alane = a_lane_addr(As, 132, q, lane);

    for (int tile = blockIdx.x; tile < ntiles; tile += gridDim.x) {
        const int base = tile * 64;
        __syncthreads();
        for (int wi = tid; wi < 2048; wi += NT) {
            int row = wi >> 5, j = (wi & 31) << 2;
            float4 v = make_float4(0.f, 0.f, 0.f, 0.f);
            if (base + row < n) {
                v = *(const float4*)(g_r + (size_t)(base + row) * HH + j);
                v.x = v.x * sc[j + 0] + sh[j + 0];
                v.y = v.y * sc[j + 1] + sh[j + 1];
                v.z = v.z * sc[j + 2] + sh[j + 2];
                v.w = v.w * sc[j + 3] + sh[j + 3];
            }
            uint4 st = make_uint4(f2tf32(v.x), f2tf32(v.y), f2tf32(v.z), f2tf32(v.w));
            *(uint4*)(As + row * 132 + j) = st;
        }
        __syncthreads();

        float acc[8][4] = {};
        #pragma unroll
        for (int ks = 0; ks < 16; ++ks) {
            uint4 a = ldsm4(alane + (ks << 5));
            #pragma unroll
            for (int p = 0; p < 4; ++p) {
                uint4 b = *(const uint4*)(Wf + ((h * 16 + ks) * 4 + p) * 132 + lane * 4);
                mma8(acc[2 * p],     a, b.x, b.y);
                mma8(acc[2 * p + 1], a, b.z, b.w);
            }
        }
        __syncthreads();   // ldsm done -> reuse As as f tile

        #pragma unroll
        for (int nt = 0; nt < 8; ++nt) {
            int col = h * 64 + 8 * nt + 2 * tg;
            *(float2*)(As + (q * 16 + g) * 132 + col) =
                make_float2(fmaxf(acc[nt][0] + bv[2 * nt], 0.f),
                            fmaxf(acc[nt][1] + bv[2 * nt + 1], 0.f));
            *(float2*)(As + (q * 16 + g + 8) * 132 + col) =
                make_float2(fmaxf(acc[nt][2] + bv[2 * nt], 0.f),
                            fmaxf(acc[nt][3] + bv[2 * nt + 1], 0.f));
        }
        __syncthreads();

        const int rw = tid >> 5;
        #pragma unroll
        for (int rr = 0; rr < 8; ++rr) {
            int row = rw * 8 + rr;
            float sAcc = 0.f;
            #pragma unroll
            for (int qq = 0; qq < 4; ++qq)
                sAcc += As[row * 132 + lane + 32 * qq] * Wo[lane + 32 * qq];
            #pragma unroll
            for (int off = 16; off; off >>= 1)
                sAcc += __shfl_xor_sync(0xffffffffu, sAcc, off);
            if (lane == 0 && base + row < n)
                out[base + row] = 1.f / (1.f + expf(-(sAcc + bo[0])));
        }
    }
}

// ---------------- launcher -----------------------------------------------------
extern "C" void kernel_launch(void* const* d_in, const int* in_sizes, int n_in,
                              void* d_out, int out_size)
{
    const float* x    = (const float*)d_in[0];
    const float* ea   = (const float*)d_in[1];
    const int*   ei   = (const int*)  d_in[2];
    const float* W0   = (const float*)d_in[4];
    const float* b0   = (const float*)d_in[5];
    const float* W1   = (const float*)d_in[6];
    const float* b1   = (const float*)d_in[7];
    const float* W1a  = (const float*)d_in[8];
    const float* b1a  = (const float*)d_in[9];
    const float* W1b  = (const float*)d_in[10];
    const float* b1b  = (const float*)d_in[11];
    const float* W2a  = (const float*)d_in[12];
    const float* b2a  = (const float*)d_in[13];
    const float* W2b  = (const float*)d_in[14];
    const float* b2b  = (const float*)d_in[15];
    const float* gam  = (const float*)d_in[16];
    const float* bet  = (const float*)d_in[17];
    const float* Wf   = (const float*)d_in[18];
    const float* bf   = (const float*)d_in[19];
    const float* Wo   = (const float*)d_in[20];
    const float* bo   = (const float*)d_in[21];
    float* out = (float*)d_out;

    const int n = in_sizes[0] / 2;
    const int E = in_sizes[2] / 2;
    const int* srcp = ei;
    const int* dstp = ei + E;

    const int ntiles_n = (n + 63) / 64;
    const int ntiles_e = (E + 63) / 64;
    const int nscan    = (n + 1023) / 1024;
    const int gPers2   = 296;
    const int gPers3   = 444;
    const int gPers4   = 592;

    const size_t SM_IN = (size_t)(16896 + 8448 + 256 + 128 + 128) * 4;
    const size_t SM_P  = (size_t)(4352 + 288) * 4;                   // 18560
    const size_t SM_E  = (size_t)(4352 + 432 + 128 + 128 + 128) * 4; // 20672
    const size_t SM_U1 = (size_t)(8448 + 64) * 4;                    // 34048
    const size_t SM_U2 = (size_t)(8448) * 4;                         // 33792
    const size_t SM_F  = (size_t)(16896 + 8448 + 256) * 4;

    cudaFuncSetAttribute(k_input, cudaFuncAttributeMaxDynamicSharedMemorySize, (int)SM_IN);
    cudaFuncSetAttribute(k_edge, cudaFuncAttributeMaxDynamicSharedMemorySize, (int)SM_E);
    cudaFuncSetAttribute(k_precompute, cudaFuncAttributeMaxDynamicSharedMemorySize, (int)SM_P);
    cudaFuncSetAttribute(k_update1, cudaFuncAttributeMaxDynamicSharedMemorySize, (int)SM_U1);
    cudaFuncSetAttribute(k_update2, cudaFuncAttributeMaxDynamicSharedMemorySize, (int)SM_U2);
    cudaFuncSetAttribute(k_final, cudaFuncAttributeMaxDynamicSharedMemorySize, (int)SM_F);

    k_init<<<1024, 256>>>(W1a, W1b, W2a, W2b, n);
    k_input<<<gPers2, NT, SM_IN>>>(x, W0, b0, W1, b1, dstp, E, n, ntiles_n);
    k_scanA<<<nscan, 1024>>>(n);
    k_scanB<<<1, 128>>>(nscan, n);
    k_scanC<<<(n + 255) / 256, 256>>>(n);
    k_sort<<<(E + 255) / 256, 256>>>(srcp, dstp, ea, E);

    for (int l = 0; l < LL; ++l) {
        const float* W1a_l  = W1a + (size_t)l * 130 * 128;
        const float* W1a_t  = W1a_l + 128 * 128;
        const float* b1a_l  = b1a + (size_t)l * 128;
        const float* b1b_l  = b1b + (size_t)l * 128;
        const float* b2a_l  = b2a + (size_t)l * 128;
        const float* b2b_l  = b2b + (size_t)l * 128;
        const float* gam_p  = (l > 0) ? gam + (size_t)(l - 1) * 128 : gam;
        const float* bet_p  = (l > 0) ? bet + (size_t)(l - 1) * 128 : bet;

        k_precompute<<<gPers3, NT, SM_P>>>(gam_p, bet_p, l, l - 1, n, ntiles_n);
        k_edge<<<gPers4, NT, SM_E>>>(W1a_t, b1a_l, l, b1b_l, E, ntiles_e);
        k_update1<<<gPers3, NT, SM_U1>>>(b2a_l, l, n, ntiles_n,
                                         (l < LL - 1) ? 1 : 0);
        k_update2<<<gPers3, NT, SM_U2>>>(b2b_l, l, n, ntiles_n);
    }

    k_final<<<gPers2, NT, SM_F>>>(Wf, bf, Wo, bo,
                                  gam + (size_t)(LL - 1) * 128,
                                  bet + (size_t)(LL - 1) * 128,
                                  LL - 1, out, n, ntiles_n);
}